// round 9
// baseline (speedup 1.0000x reference)
#include <cuda_runtime.h>
#include <math.h>

#define EPS 1e-5f
typedef unsigned long long ull;

// ---------------- f32x2 packed helpers ----------------
__device__ __forceinline__ ull pk2(float lo, float hi) {
    ull r; asm("mov.b64 %0,{%1,%2};" : "=l"(r) : "f"(lo), "f"(hi)); return r;
}
__device__ __forceinline__ void unpk2(float& lo, float& hi, ull v) {
    asm("mov.b64 {%0,%1},%2;" : "=f"(lo), "=f"(hi) : "l"(v));
}
__device__ __forceinline__ ull fma2(ull a, ull b, ull c) {
    ull d; asm("fma.rn.f32x2 %0,%1,%2,%3;" : "=l"(d) : "l"(a), "l"(b), "l"(c)); return d;
}

// ---------------- scratch (device globals; no allocations) ----------------
__device__ float g_xn[512 * 768];
__device__ float g_qkv[512 * 2304];
__device__ float g_qh[12 * 512 * 64];    // [h][i][d], q * scale
__device__ float g_kT[12 * 64 * 512];    // [h][d][j]
__device__ float g_vh[12 * 512 * 64];    // [h][j][d]
__device__ __align__(16) float g_gW[768 * 12];  // pair_g[c] * Wbias[c][h]
__device__ float g_GW[12];
__device__ float g_BW[12];
__device__ float g_bias[12 * 512 * 512]; // [h][i][j]; j>i stays 0 (.bss)
__device__ float g_sim[12 * 512 * 512];  // [h][i][j], reused as attn
__device__ float g_attout[512 * 768];    // [i][h*64+d]

// ---------------- precompute gW, GW, BW ----------------
__global__ void precompute_gw(const float* __restrict__ pg,
                              const float* __restrict__ pb,
                              const float* __restrict__ Wb) {
    int t = threadIdx.x; // 384
    for (int idx = t; idx < 768 * 12; idx += 384)
        g_gW[idx] = pg[idx / 12] * Wb[idx];
    int w = t >> 5, l = t & 31;
    if (w < 12) {
        float gw = 0.f, bw = 0.f;
        for (int c = l; c < 768; c += 32) {
            float wv = Wb[c * 12 + w];
            gw = fmaf(pg[c], wv, gw);
            bw = fmaf(pb[c], wv, bw);
        }
#pragma unroll
        for (int o = 16; o; o >>= 1) {
            gw += __shfl_xor_sync(0xffffffffu, gw, o);
            bw += __shfl_xor_sync(0xffffffffu, bw, o);
        }
        if (l == 0) { g_GW[w] = gw; g_BW[w] = bw; }
    }
}

// ---------------- LN(x) -> g_xn ----------------
__global__ void __launch_bounds__(192) ln_x_kernel(const float* __restrict__ x,
                                                   const float* __restrict__ g,
                                                   const float* __restrict__ b) {
    int i = blockIdx.x, t = threadIdx.x;
    int c = t * 4;
    float4 xv = *(const float4*)(x + i * 768 + c);
    float s = xv.x + xv.y + xv.z + xv.w;
    float ss = xv.x * xv.x + xv.y * xv.y + xv.z * xv.z + xv.w * xv.w;
    int lane = t & 31, w = t >> 5;
#pragma unroll
    for (int o = 16; o; o >>= 1) {
        s += __shfl_xor_sync(0xffffffffu, s, o);
        ss += __shfl_xor_sync(0xffffffffu, ss, o);
    }
    __shared__ float sh[6][2];
    if (lane == 0) { sh[w][0] = s; sh[w][1] = ss; }
    __syncthreads();
    float S = 0.f, SS = 0.f;
#pragma unroll
    for (int q = 0; q < 6; q++) { S += sh[q][0]; SS += sh[q][1]; }
    float m = S * (1.f / 768.f);
    float r = rsqrtf(SS * (1.f / 768.f) - m * m + EPS);
    float4 gv = *(const float4*)(g + c);
    float4 bv = *(const float4*)(b + c);
    float4 o;
    o.x = (xv.x - m) * r * gv.x + bv.x;
    o.y = (xv.y - m) * r * gv.y + bv.y;
    o.z = (xv.z - m) * r * gv.z + bv.z;
    o.w = (xv.w - m) * r * gv.w + bv.w;
    *(float4*)(g_xn + i * 768 + c) = o;
}

// ---------------- qkv split: QK-LN + head reshapes ----------------
__global__ void __launch_bounds__(192) qkv_prep_kernel(const float* __restrict__ qg,
                                                       const float* __restrict__ qb,
                                                       const float* __restrict__ kg,
                                                       const float* __restrict__ kb) {
    int i = blockIdx.x, p = blockIdx.y, t = threadIdx.x;
    int c = t * 4;
    const float* row = g_qkv + i * 2304 + p * 768;
    float4 xv = *(const float4*)(row + c);
    int h = c >> 6, d = c & 63;
    if (p == 2) {
        *(float4*)(g_vh + (h * 512 + i) * 64 + d) = xv;
        return;
    }
    float s = xv.x + xv.y + xv.z + xv.w;
    float ss = xv.x * xv.x + xv.y * xv.y + xv.z * xv.z + xv.w * xv.w;
    int lane = t & 31, w = t >> 5;
#pragma unroll
    for (int o = 16; o; o >>= 1) {
        s += __shfl_xor_sync(0xffffffffu, s, o);
        ss += __shfl_xor_sync(0xffffffffu, ss, o);
    }
    __shared__ float sh[6][2];
    if (lane == 0) { sh[w][0] = s; sh[w][1] = ss; }
    __syncthreads();
    float S = 0.f, SS = 0.f;
#pragma unroll
    for (int q = 0; q < 6; q++) { S += sh[q][0]; SS += sh[q][1]; }
    float m = S * (1.f / 768.f);
    float r = rsqrtf(SS * (1.f / 768.f) - m * m + EPS);
    const float* gg = (p == 0) ? qg : kg;
    const float* bb = (p == 0) ? qb : kb;
    float4 gv = *(const float4*)(gg + c);
    float4 bv = *(const float4*)(bb + c);
    float v0 = (xv.x - m) * r * gv.x + bv.x;
    float v1 = (xv.y - m) * r * gv.y + bv.y;
    float v2 = (xv.z - m) * r * gv.z + bv.z;
    float v3 = (xv.w - m) * r * gv.w + bv.w;
    if (p == 0) {
        float4 o = make_float4(v0 * 0.125f, v1 * 0.125f, v2 * 0.125f, v3 * 0.125f);
        *(float4*)(g_qh + (h * 512 + i) * 64 + d) = o;
    } else {
        float* kp = g_kT + h * (64 * 512) + d * 512 + i;
        kp[0] = v0; kp[512] = v1; kp[1024] = v2; kp[1536] = v3;
    }
}

// ---------------- pair-bias v3: triangle tiles, row-per-lane, L1 weights ---
// grid (8, 512): 64-row tile jt for query i. Block 64 thr = 2 warps.
// Warp w: rows j = jt*64 + w*32 + lane, one row per lane, no reductions.
// Weights: 3x LDG.128 per channel (warp-uniform -> L1 broadcast), already
// bit-packed as f32x2 pairs. Rows staged via 2KB warp-private smem.
__global__ void __launch_bounds__(64) pair_bias_kernel(const float* __restrict__ pair) {
    int jt = blockIdx.x, i = blockIdx.y;
    int j0 = jt * 64;
    if (j0 > i) return;
    int w = threadIdx.x >> 5, lane = threadIdx.x & 31;
    int j = j0 + w * 32 + lane;
    bool live = (j <= i);

    __shared__ float sx[2][16 * 33];
    float* sxw = sx[w];

    const size_t rowbase = (size_t)i * 512;
    const float* lptr[4];
#pragma unroll
    for (int p = 0; p < 4; p++) {
        int flat = lane + 32 * p;
        int r = flat >> 2, seg = flat & 3;
        int jr = j0 + w * 32 + r; if (jr > i) jr = i;
        lptr[p] = pair + (rowbase + jr) * 768 + seg * 4;
    }

    ull S[6] = {0, 0, 0, 0, 0, 0};
    float s = 0.f, ss = 0.f;

    float4 pf[4];
#pragma unroll
    for (int p = 0; p < 4; p++) pf[p] = *(const float4*)(lptr[p]);

    for (int cc = 0; cc < 48; cc++) {
        __syncwarp();                        // prior compute done before overwrite
#pragma unroll
        for (int p = 0; p < 4; p++) {
            int flat = lane + 32 * p;
            int r = flat >> 2, seg = flat & 3;
            sxw[(seg * 4 + 0) * 33 + r] = pf[p].x;
            sxw[(seg * 4 + 1) * 33 + r] = pf[p].y;
            sxw[(seg * 4 + 2) * 33 + r] = pf[p].z;
            sxw[(seg * 4 + 3) * 33 + r] = pf[p].w;
        }
        __syncwarp();
        if (cc + 1 < 48) {
            int off = (cc + 1) * 16;
#pragma unroll
            for (int p = 0; p < 4; p++) pf[p] = *(const float4*)(lptr[p] + off);
        }
#pragma unroll 4
        for (int c = 0; c < 16; c++) {
            int ch = cc * 16 + c;
            const ulonglong2* wp = (const ulonglong2*)(g_gW + ch * 12);
            ulonglong2 q0 = __ldg(wp);
            ulonglong2 q1 = __ldg(wp + 1);
            ulonglong2 q2 = __ldg(wp + 2);
            float x = sxw[c * 33 + lane];
            s += x; ss = fmaf(x, x, ss);
            ull px = pk2(x, x);
            S[0] = fma2(px, q0.x, S[0]); S[1] = fma2(px, q0.y, S[1]);
            S[2] = fma2(px, q1.x, S[2]); S[3] = fma2(px, q1.y, S[3]);
            S[4] = fma2(px, q2.x, S[4]); S[5] = fma2(px, q2.y, S[5]);
        }
    }
    if (!live) return;
    float m = s * (1.f / 768.f);
    float r = rsqrtf(ss * (1.f / 768.f) - m * m + EPS);
    size_t pos = rowbase + j;
#pragma unroll
    for (int h2 = 0; h2 < 6; h2++) {
        float lo, hi; unpk2(lo, hi, S[h2]);
        g_bias[(size_t)(2 * h2) * (512 * 512) + pos] =
            r * (lo - m * __ldg(&g_GW[2 * h2])) + __ldg(&g_BW[2 * h2]);
        g_bias[(size_t)(2 * h2 + 1) * (512 * 512) + pos] =
            r * (hi - m * __ldg(&g_GW[2 * h2 + 1])) + __ldg(&g_BW[2 * h2 + 1]);
    }
}

// ---------------- f32x2 GEMM (R6 known-good): N-packed acc, double-buffered
template <int BM, int BN, int TM, int TN>
__device__ __forceinline__ void gemm2_body(const float* __restrict__ A,
                                           const float* __restrict__ B,
                                           float* __restrict__ C,
                                           const float* __restrict__ biasRow,
                                           const float* __restrict__ biasMat,
                                           int K, int lda, int ldb, int ldc) {
    constexpr int THREADS = (BM / TM) * (BN / TN);
    static_assert(THREADS == 256 && TM == 4, "shape");
    __shared__ __align__(16) float As[2][8][BM];
    __shared__ __align__(16) float Bs[2][8][BN];

    int tid = threadIdx.x;
    int tx = tid % (BN / TN), ty = tid / (BN / TN);
    int m0 = blockIdx.y * BM, n0 = blockIdx.x * BN;

    ull acc[TM][TN / 2];
#pragma unroll
    for (int ii = 0; ii < TM; ii++)
#pragma unroll
        for (int j2 = 0; j2 < TN / 2; j2++) acc[ii][j2] = 0ull;

    bool aact = tid < 2 * BM;
    bool bact = tid < 2 * BN;
    int ar = tid >> 1, ac = (tid & 1) * 4;
    int br = tid / (BN / 4), bc = (tid % (BN / 4)) * 4;

    float4 pa = make_float4(0.f, 0.f, 0.f, 0.f), pb = pa;
    if (aact) pa = *(const float4*)(A + (size_t)(m0 + ar) * lda + ac);
    if (bact) pb = *(const float4*)(B + (size_t)br * ldb + n0 + bc);
    if (aact) {
        As[0][ac + 0][ar] = pa.x; As[0][ac + 1][ar] = pa.y;
        As[0][ac + 2][ar] = pa.z; As[0][ac + 3][ar] = pa.w;
    }
    if (bact) *(float4*)&Bs[0][br][bc] = pb;
    __syncthreads();

    int sb = 0;
    for (int k0 = 0; k0 < K; k0 += 8) {
        bool more = (k0 + 8 < K);
        if (more) {
            if (aact) pa = *(const float4*)(A + (size_t)(m0 + ar) * lda + k0 + 8 + ac);
            if (bact) pb = *(const float4*)(B + (size_t)(k0 + 8 + br) * ldb + n0 + bc);
        }
#pragma unroll
        for (int kk = 0; kk < 8; kk++) {
            float4 av = *(const float4*)&As[sb][kk][ty * TM];
            float a4[4] = {av.x, av.y, av.z, av.w};
            ull b2[TN / 2];
            const ull* bp = (const ull*)&Bs[sb][kk][tx * TN];
#pragma unroll
            for (int j2 = 0; j2 < TN / 2; j2++) b2[j2] = bp[j2];
#pragma unroll
            for (int ii = 0; ii < TM; ii++) {
                ull aa = pk2(a4[ii], a4[ii]);
#pragma unroll
                for (int j2 = 0; j2 < TN / 2; j2++)
                    acc[ii][j2] = fma2(aa, b2[j2], acc[ii][j2]);
            }
        }
        if (more) {
            if (aact) {
                As[sb ^ 1][ac + 0][ar] = pa.x; As[sb ^ 1][ac + 1][ar] = pa.y;
                As[sb ^ 1][ac + 2][ar] = pa.z; As[sb ^ 1][ac + 3][ar] = pa.w;
            }
            if (bact) *(float4*)&Bs[sb ^ 1][br][bc] = pb;
            __syncthreads();
            sb ^= 1;
        }
    }

    float bv[TN];
#pragma unroll
    for (int c = 0; c < TN; c++)
        bv[c] = biasRow ? biasRow[n0 + tx * TN + c] : 0.f;

#pragma unroll
    for (int ii = 0; ii < TM; ii++) {
        int r = m0 + ty * TM + ii;
        float o[TN];
#pragma unroll
        for (int j2 = 0; j2 < TN / 2; j2++) {
            unpk2(o[2 * j2], o[2 * j2 + 1], acc[ii][j2]);
            o[2 * j2] += bv[2 * j2];
            o[2 * j2 + 1] += bv[2 * j2 + 1];
        }
        if (biasMat) {
            const float* bm = biasMat + (size_t)r * ldc + n0 + tx * TN;
#pragma unroll
            for (int c4 = 0; c4 < TN / 4; c4++) {
                float4 mv = *(const float4*)(bm + 4 * c4);
                o[4*c4+0] += mv.x; o[4*c4+1] += mv.y;
                o[4*c4+2] += mv.z; o[4*c4+3] += mv.w;
            }
        }
        float* cp = C + (size_t)r * ldc + n0 + tx * TN;
#pragma unroll
        for (int c4 = 0; c4 < TN / 4; c4++)
            *(float4*)(cp + 4 * c4) = make_float4(o[4*c4], o[4*c4+1], o[4*c4+2], o[4*c4+3]);
    }
}

__global__ void __launch_bounds__(256) gemm_qkv(const float* __restrict__ W,
                                                const float* __restrict__ bias) {
    gemm2_body<64, 64, 4, 4>(g_xn, W, g_qkv, bias, nullptr, 768, 768, 2304, 2304);
}
__global__ void __launch_bounds__(256) gemm_qk() {
    int h = blockIdx.z;
    gemm2_body<64, 128, 4, 8>(g_qh + h * (512 * 64), g_kT + h * (64 * 512),
                              g_sim + (size_t)h * (512 * 512), nullptr,
                              g_bias + (size_t)h * (512 * 512), 64, 64, 512, 512);
}
__global__ void __launch_bounds__(256) gemm_pv() {
    int h = blockIdx.z;
    gemm2_body<64, 64, 4, 4>(g_sim + (size_t)h * (512 * 512), g_vh + h * (512 * 64),
                             g_attout + h * 64, nullptr, nullptr, 512, 512, 64, 768);
}
__global__ void __launch_bounds__(256) gemm_proj(const float* __restrict__ W,
                                                 const float* __restrict__ bias,
                                                 float* __restrict__ out) {
    gemm2_body<64, 64, 4, 4>(g_attout, W, out, bias, nullptr, 768, 768, 768, 768);
}

// ---------------- softmax: warp per (h,i) row, registers only ----------------
__global__ void __launch_bounds__(256) softmax_kernel() {
    int warp = threadIdx.x >> 5, lane = threadIdx.x & 31;
    int rowid = blockIdx.x * 8 + warp;              // 0..6143
    float* row = g_sim + (size_t)rowid * 512;
    float v[16];
    float4* rp = (float4*)(row + lane * 16);
    float4 r0 = rp[0], r1 = rp[1], r2 = rp[2], r3 = rp[3];
    v[0]=r0.x; v[1]=r0.y; v[2]=r0.z; v[3]=r0.w;
    v[4]=r1.x; v[5]=r1.y; v[6]=r1.z; v[7]=r1.w;
    v[8]=r2.x; v[9]=r2.y; v[10]=r2.z; v[11]=r2.w;
    v[12]=r3.x; v[13]=r3.y; v[14]=r3.z; v[15]=r3.w;
    float m = v[0];
#pragma unroll
    for (int e = 1; e < 16; e++) m = fmaxf(m, v[e]);
#pragma unroll
    for (int o = 16; o; o >>= 1) m = fmaxf(m, __shfl_xor_sync(0xffffffffu, m, o));
    float s = 0.f;
#pragma unroll
    for (int e = 0; e < 16; e++) { v[e] = __expf(v[e] - m); s += v[e]; }
#pragma unroll
    for (int o = 16; o; o >>= 1) s += __shfl_xor_sync(0xffffffffu, s, o);
    float inv = __fdividef(1.f, s);
    rp[0] = make_float4(v[0]*inv, v[1]*inv, v[2]*inv, v[3]*inv);
    rp[1] = make_float4(v[4]*inv, v[5]*inv, v[6]*inv, v[7]*inv);
    rp[2] = make_float4(v[8]*inv, v[9]*inv, v[10]*inv, v[11]*inv);
    rp[3] = make_float4(v[12]*inv, v[13]*inv, v[14]*inv, v[15]*inv);
}

// ---------------- launch ----------------
extern "C" void kernel_launch(void* const* d_in, const int* in_sizes, int n_in,
                              void* d_out, int out_size) {
    int base = n_in - 13;                     // norm_g index (mask-type agnostic)
    const float* x      = (const float*)d_in[0];
    const float* pair   = (const float*)d_in[1];
    const float* norm_g = (const float*)d_in[base + 0];
    const float* norm_b = (const float*)d_in[base + 1];
    const float* Wqkv   = (const float*)d_in[base + 2];
    const float* bqkv   = (const float*)d_in[base + 3];
    const float* qln_g  = (const float*)d_in[base + 4];
    const float* qln_b  = (const float*)d_in[base + 5];
    const float* kln_g  = (const float*)d_in[base + 6];
    const float* kln_b  = (const float*)d_in[base + 7];
    const float* pair_g = (const float*)d_in[base + 8];
    const float* pair_b = (const float*)d_in[base + 9];
    const float* Wbias  = (const float*)d_in[base + 10];
    const float* Wproj  = (const float*)d_in[base + 11];
    const float* bproj  = (const float*)d_in[base + 12];
    float* out = (float*)d_out;

    precompute_gw<<<1, 384>>>(pair_g, pair_b, Wbias);              // 1
    ln_x_kernel<<<512, 192>>>(x, norm_g, norm_b);                  // 2
    gemm_qkv<<<dim3(36, 8), 256>>>(Wqkv, bqkv);                    // 3
    pair_bias_kernel<<<dim3(8, 512), 64>>>(pair);                  // 4 <- profiled
    qkv_prep_kernel<<<dim3(512, 3), 192>>>(qln_g, qln_b, kln_g, kln_b); // 5
    gemm_qk<<<dim3(4, 8, 12), 256>>>();                            // 6
    softmax_kernel<<<768, 256>>>();                                // 7
    gemm_pv<<<dim3(1, 8, 12), 256>>>();                            // 8
    gemm_proj<<<dim3(12, 8), 256>>>(Wproj, bproj, out);            // 9
}

// round 10
// speedup vs baseline: 1.0414x; 1.0414x over previous
#include <cuda_runtime.h>
#include <math.h>

#define EPS 1e-5f
typedef unsigned long long ull;

// ---------------- f32x2 packed helpers ----------------
__device__ __forceinline__ ull pk2(float lo, float hi) {
    ull r; asm("mov.b64 %0,{%1,%2};" : "=l"(r) : "f"(lo), "f"(hi)); return r;
}
__device__ __forceinline__ void unpk2(float& lo, float& hi, ull v) {
    asm("mov.b64 {%0,%1},%2;" : "=f"(lo), "=f"(hi) : "l"(v));
}
__device__ __forceinline__ ull fma2(ull a, ull b, ull c) {
    ull d; asm("fma.rn.f32x2 %0,%1,%2,%3;" : "=l"(d) : "l"(a), "l"(b), "l"(c)); return d;
}

// ---------------- scratch (device globals; no allocations) ----------------
__device__ float g_xn[512 * 768];
__device__ float g_qkv[512 * 2304];
__device__ float g_qh[12 * 512 * 64];    // [h][i][d], q * scale
__device__ float g_kT[12 * 64 * 512];    // [h][d][j]
__device__ float g_vh[12 * 512 * 64];    // [h][j][d]
__device__ __align__(16) float g_gW[768 * 12];  // pair_g[c] * Wbias[c][h]
__device__ float g_GW[12];
__device__ float g_BW[12];
__device__ float g_bias[12 * 512 * 512]; // [h][i][j]; j>i stays 0 (.bss)
__device__ float g_sim[12 * 512 * 512];  // [h][i][j], reused as attn
__device__ float g_attout[512 * 768];    // [i][h*64+d]

// ---------------- precompute gW, GW, BW ----------------
__global__ void precompute_gw(const float* __restrict__ pg,
                              const float* __restrict__ pb,
                              const float* __restrict__ Wb) {
    int t = threadIdx.x; // 384
    for (int idx = t; idx < 768 * 12; idx += 384)
        g_gW[idx] = pg[idx / 12] * Wb[idx];
    int w = t >> 5, l = t & 31;
    if (w < 12) {
        float gw = 0.f, bw = 0.f;
        for (int c = l; c < 768; c += 32) {
            float wv = Wb[c * 12 + w];
            gw = fmaf(pg[c], wv, gw);
            bw = fmaf(pb[c], wv, bw);
        }
#pragma unroll
        for (int o = 16; o; o >>= 1) {
            gw += __shfl_xor_sync(0xffffffffu, gw, o);
            bw += __shfl_xor_sync(0xffffffffu, bw, o);
        }
        if (l == 0) { g_GW[w] = gw; g_BW[w] = bw; }
    }
}

// ---------------- LN(x) -> g_xn ----------------
__global__ void __launch_bounds__(192) ln_x_kernel(const float* __restrict__ x,
                                                   const float* __restrict__ g,
                                                   const float* __restrict__ b) {
    int i = blockIdx.x, t = threadIdx.x;
    int c = t * 4;
    float4 xv = *(const float4*)(x + i * 768 + c);
    float s = xv.x + xv.y + xv.z + xv.w;
    float ss = xv.x * xv.x + xv.y * xv.y + xv.z * xv.z + xv.w * xv.w;
    int lane = t & 31, w = t >> 5;
#pragma unroll
    for (int o = 16; o; o >>= 1) {
        s += __shfl_xor_sync(0xffffffffu, s, o);
        ss += __shfl_xor_sync(0xffffffffu, ss, o);
    }
    __shared__ float sh[6][2];
    if (lane == 0) { sh[w][0] = s; sh[w][1] = ss; }
    __syncthreads();
    float S = 0.f, SS = 0.f;
#pragma unroll
    for (int q = 0; q < 6; q++) { S += sh[q][0]; SS += sh[q][1]; }
    float m = S * (1.f / 768.f);
    float r = rsqrtf(SS * (1.f / 768.f) - m * m + EPS);
    float4 gv = *(const float4*)(g + c);
    float4 bv = *(const float4*)(b + c);
    float4 o;
    o.x = (xv.x - m) * r * gv.x + bv.x;
    o.y = (xv.y - m) * r * gv.y + bv.y;
    o.z = (xv.z - m) * r * gv.z + bv.z;
    o.w = (xv.w - m) * r * gv.w + bv.w;
    *(float4*)(g_xn + i * 768 + c) = o;
}

// ---------------- qkv split: QK-LN + head reshapes ----------------
__global__ void __launch_bounds__(192) qkv_prep_kernel(const float* __restrict__ qg,
                                                       const float* __restrict__ qb,
                                                       const float* __restrict__ kg,
                                                       const float* __restrict__ kb) {
    int i = blockIdx.x, p = blockIdx.y, t = threadIdx.x;
    int c = t * 4;
    const float* row = g_qkv + i * 2304 + p * 768;
    float4 xv = *(const float4*)(row + c);
    int h = c >> 6, d = c & 63;
    if (p == 2) {
        *(float4*)(g_vh + (h * 512 + i) * 64 + d) = xv;
        return;
    }
    float s = xv.x + xv.y + xv.z + xv.w;
    float ss = xv.x * xv.x + xv.y * xv.y + xv.z * xv.z + xv.w * xv.w;
    int lane = t & 31, w = t >> 5;
#pragma unroll
    for (int o = 16; o; o >>= 1) {
        s += __shfl_xor_sync(0xffffffffu, s, o);
        ss += __shfl_xor_sync(0xffffffffu, ss, o);
    }
    __shared__ float sh[6][2];
    if (lane == 0) { sh[w][0] = s; sh[w][1] = ss; }
    __syncthreads();
    float S = 0.f, SS = 0.f;
#pragma unroll
    for (int q = 0; q < 6; q++) { S += sh[q][0]; SS += sh[q][1]; }
    float m = S * (1.f / 768.f);
    float r = rsqrtf(SS * (1.f / 768.f) - m * m + EPS);
    const float* gg = (p == 0) ? qg : kg;
    const float* bb = (p == 0) ? qb : kb;
    float4 gv = *(const float4*)(gg + c);
    float4 bv = *(const float4*)(bb + c);
    float v0 = (xv.x - m) * r * gv.x + bv.x;
    float v1 = (xv.y - m) * r * gv.y + bv.y;
    float v2 = (xv.z - m) * r * gv.z + bv.z;
    float v3 = (xv.w - m) * r * gv.w + bv.w;
    if (p == 0) {
        float4 o = make_float4(v0 * 0.125f, v1 * 0.125f, v2 * 0.125f, v3 * 0.125f);
        *(float4*)(g_qh + (h * 512 + i) * 64 + d) = o;
    } else {
        float* kp = g_kT + h * (64 * 512) + d * 512 + i;
        kp[0] = v0; kp[512] = v1; kp[1024] = v2; kp[1536] = v3;
    }
}

// ---------------- pair-bias v4: row-per-lane, smem weights, reg-direct x ---
// Block 256 thr (8 warps) covers a 256-row j-tile for query i; grid (2, 512).
// Warp w owns rows j = jt*256 + w*32 + lane. Weights copied once to smem as
// raw ull (already f32x2-packed pairs); 3 LDS.128 per channel (broadcast).
// x read straight to registers: 1 LDG.128 per 4 channels per lane (32B
// sectors fully used). No reductions, no staging, no spill-prone state.
__global__ void __launch_bounds__(256) pair_bias_kernel(const float* __restrict__ pair) {
    int jt = blockIdx.x, i = blockIdx.y;
    if (jt * 256 > i) return;                 // block-uniform dead exit
    __shared__ __align__(16) ull sgW[4608];   // 36 KB
    {
        const ull* src = (const ull*)g_gW;
        for (int idx = threadIdx.x; idx < 4608; idx += 256)
            sgW[idx] = src[idx];
    }
    __syncthreads();

    int w = threadIdx.x >> 5, lane = threadIdx.x & 31;
    int jw = jt * 256 + w * 32;
    if (jw > i) return;                       // dead warp (after the sync)
    int j = jw + lane;
    bool live = (j <= i);
    int jc = live ? j : i;                    // clamped row: warp-broadcast read

    const float* xr = pair + ((size_t)i * 512 + jc) * 768;
    ull S[6] = {0, 0, 0, 0, 0, 0};
    float s = 0.f, ss = 0.f;

    float4 xf = *(const float4*)xr;
#pragma unroll 1
    for (int c0 = 0; c0 < 768; c0 += 4) {
        float xs[4] = {xf.x, xf.y, xf.z, xf.w};
        if (c0 + 4 < 768) xf = *(const float4*)(xr + c0 + 4);
#pragma unroll
        for (int k = 0; k < 4; k++) {
            const ulonglong2* wp = (const ulonglong2*)&sgW[(c0 + k) * 6];
            ulonglong2 q0 = wp[0];
            ulonglong2 q1 = wp[1];
            ulonglong2 q2 = wp[2];
            float x = xs[k];
            s += x; ss = fmaf(x, x, ss);
            ull px = pk2(x, x);
            S[0] = fma2(px, q0.x, S[0]); S[1] = fma2(px, q0.y, S[1]);
            S[2] = fma2(px, q1.x, S[2]); S[3] = fma2(px, q1.y, S[3]);
            S[4] = fma2(px, q2.x, S[4]); S[5] = fma2(px, q2.y, S[5]);
        }
    }
    if (!live) return;
    float m = s * (1.f / 768.f);
    float r = rsqrtf(ss * (1.f / 768.f) - m * m + EPS);
    size_t pos = (size_t)i * 512 + j;
#pragma unroll
    for (int h2 = 0; h2 < 6; h2++) {
        float lo, hi; unpk2(lo, hi, S[h2]);
        g_bias[(size_t)(2 * h2) * (512 * 512) + pos] =
            r * (lo - m * __ldg(&g_GW[2 * h2])) + __ldg(&g_BW[2 * h2]);
        g_bias[(size_t)(2 * h2 + 1) * (512 * 512) + pos] =
            r * (hi - m * __ldg(&g_GW[2 * h2 + 1])) + __ldg(&g_BW[2 * h2 + 1]);
    }
}

// ---------------- f32x2 GEMM (R6 known-good): N-packed acc, double-buffered
template <int BM, int BN, int TM, int TN>
__device__ __forceinline__ void gemm2_body(const float* __restrict__ A,
                                           const float* __restrict__ B,
                                           float* __restrict__ C,
                                           const float* __restrict__ biasRow,
                                           const float* __restrict__ biasMat,
                                           int K, int lda, int ldb, int ldc) {
    constexpr int THREADS = (BM / TM) * (BN / TN);
    static_assert(THREADS == 256 && TM == 4, "shape");
    __shared__ __align__(16) float As[2][8][BM];
    __shared__ __align__(16) float Bs[2][8][BN];

    int tid = threadIdx.x;
    int tx = tid % (BN / TN), ty = tid / (BN / TN);
    int m0 = blockIdx.y * BM, n0 = blockIdx.x * BN;

    ull acc[TM][TN / 2];
#pragma unroll
    for (int ii = 0; ii < TM; ii++)
#pragma unroll
        for (int j2 = 0; j2 < TN / 2; j2++) acc[ii][j2] = 0ull;

    bool aact = tid < 2 * BM;
    bool bact = tid < 2 * BN;
    int ar = tid >> 1, ac = (tid & 1) * 4;
    int br = tid / (BN / 4), bc = (tid % (BN / 4)) * 4;

    float4 pa = make_float4(0.f, 0.f, 0.f, 0.f), pb = pa;
    if (aact) pa = *(const float4*)(A + (size_t)(m0 + ar) * lda + ac);
    if (bact) pb = *(const float4*)(B + (size_t)br * ldb + n0 + bc);
    if (aact) {
        As[0][ac + 0][ar] = pa.x; As[0][ac + 1][ar] = pa.y;
        As[0][ac + 2][ar] = pa.z; As[0][ac + 3][ar] = pa.w;
    }
    if (bact) *(float4*)&Bs[0][br][bc] = pb;
    __syncthreads();

    int sb = 0;
    for (int k0 = 0; k0 < K; k0 += 8) {
        bool more = (k0 + 8 < K);
        if (more) {
            if (aact) pa = *(const float4*)(A + (size_t)(m0 + ar) * lda + k0 + 8 + ac);
            if (bact) pb = *(const float4*)(B + (size_t)(k0 + 8 + br) * ldb + n0 + bc);
        }
#pragma unroll
        for (int kk = 0; kk < 8; kk++) {
            float4 av = *(const float4*)&As[sb][kk][ty * TM];
            float a4[4] = {av.x, av.y, av.z, av.w};
            ull b2[TN / 2];
            const ull* bp = (const ull*)&Bs[sb][kk][tx * TN];
#pragma unroll
            for (int j2 = 0; j2 < TN / 2; j2++) b2[j2] = bp[j2];
#pragma unroll
            for (int ii = 0; ii < TM; ii++) {
                ull aa = pk2(a4[ii], a4[ii]);
#pragma unroll
                for (int j2 = 0; j2 < TN / 2; j2++)
                    acc[ii][j2] = fma2(aa, b2[j2], acc[ii][j2]);
            }
        }
        if (more) {
            if (aact) {
                As[sb ^ 1][ac + 0][ar] = pa.x; As[sb ^ 1][ac + 1][ar] = pa.y;
                As[sb ^ 1][ac + 2][ar] = pa.z; As[sb ^ 1][ac + 3][ar] = pa.w;
            }
            if (bact) *(float4*)&Bs[sb ^ 1][br][bc] = pb;
            __syncthreads();
            sb ^= 1;
        }
    }

    float bv[TN];
#pragma unroll
    for (int c = 0; c < TN; c++)
        bv[c] = biasRow ? biasRow[n0 + tx * TN + c] : 0.f;

#pragma unroll
    for (int ii = 0; ii < TM; ii++) {
        int r = m0 + ty * TM + ii;
        float o[TN];
#pragma unroll
        for (int j2 = 0; j2 < TN / 2; j2++) {
            unpk2(o[2 * j2], o[2 * j2 + 1], acc[ii][j2]);
            o[2 * j2] += bv[2 * j2];
            o[2 * j2 + 1] += bv[2 * j2 + 1];
        }
        if (biasMat) {
            const float* bm = biasMat + (size_t)r * ldc + n0 + tx * TN;
#pragma unroll
            for (int c4 = 0; c4 < TN / 4; c4++) {
                float4 mv = *(const float4*)(bm + 4 * c4);
                o[4*c4+0] += mv.x; o[4*c4+1] += mv.y;
                o[4*c4+2] += mv.z; o[4*c4+3] += mv.w;
            }
        }
        float* cp = C + (size_t)r * ldc + n0 + tx * TN;
#pragma unroll
        for (int c4 = 0; c4 < TN / 4; c4++)
            *(float4*)(cp + 4 * c4) = make_float4(o[4*c4], o[4*c4+1], o[4*c4+2], o[4*c4+3]);
    }
}

__global__ void __launch_bounds__(256) gemm_qkv(const float* __restrict__ W,
                                                const float* __restrict__ bias) {
    gemm2_body<64, 64, 4, 4>(g_xn, W, g_qkv, bias, nullptr, 768, 768, 2304, 2304);
}
__global__ void __launch_bounds__(256) gemm_qk() {
    int h = blockIdx.z;
    gemm2_body<64, 128, 4, 8>(g_qh + h * (512 * 64), g_kT + h * (64 * 512),
                              g_sim + (size_t)h * (512 * 512), nullptr,
                              g_bias + (size_t)h * (512 * 512), 64, 64, 512, 512);
}
__global__ void __launch_bounds__(256) gemm_pv() {
    int h = blockIdx.z;
    gemm2_body<64, 64, 4, 4>(g_sim + (size_t)h * (512 * 512), g_vh + h * (512 * 64),
                             g_attout + h * 64, nullptr, nullptr, 512, 512, 64, 768);
}
__global__ void __launch_bounds__(256) gemm_proj(const float* __restrict__ W,
                                                 const float* __restrict__ bias,
                                                 float* __restrict__ out) {
    gemm2_body<64, 64, 4, 4>(g_attout, W, out, bias, nullptr, 768, 768, 768, 768);
}

// ---------------- softmax: warp per (h,i) row, registers only ----------------
__global__ void __launch_bounds__(256) softmax_kernel() {
    int warp = threadIdx.x >> 5, lane = threadIdx.x & 31;
    int rowid = blockIdx.x * 8 + warp;              // 0..6143
    float* row = g_sim + (size_t)rowid * 512;
    float v[16];
    float4* rp = (float4*)(row + lane * 16);
    float4 r0 = rp[0], r1 = rp[1], r2 = rp[2], r3 = rp[3];
    v[0]=r0.x; v[1]=r0.y; v[2]=r0.z; v[3]=r0.w;
    v[4]=r1.x; v[5]=r1.y; v[6]=r1.z; v[7]=r1.w;
    v[8]=r2.x; v[9]=r2.y; v[10]=r2.z; v[11]=r2.w;
    v[12]=r3.x; v[13]=r3.y; v[14]=r3.z; v[15]=r3.w;
    float m = v[0];
#pragma unroll
    for (int e = 1; e < 16; e++) m = fmaxf(m, v[e]);
#pragma unroll
    for (int o = 16; o; o >>= 1) m = fmaxf(m, __shfl_xor_sync(0xffffffffu, m, o));
    float s = 0.f;
#pragma unroll
    for (int e = 0; e < 16; e++) { v[e] = __expf(v[e] - m); s += v[e]; }
#pragma unroll
    for (int o = 16; o; o >>= 1) s += __shfl_xor_sync(0xffffffffu, s, o);
    float inv = __fdividef(1.f, s);
    rp[0] = make_float4(v[0]*inv, v[1]*inv, v[2]*inv, v[3]*inv);
    rp[1] = make_float4(v[4]*inv, v[5]*inv, v[6]*inv, v[7]*inv);
    rp[2] = make_float4(v[8]*inv, v[9]*inv, v[10]*inv, v[11]*inv);
    rp[3] = make_float4(v[12]*inv, v[13]*inv, v[14]*inv, v[15]*inv);
}

// ---------------- launch ----------------
extern "C" void kernel_launch(void* const* d_in, const int* in_sizes, int n_in,
                              void* d_out, int out_size) {
    int base = n_in - 13;                     // norm_g index (mask-type agnostic)
    const float* x      = (const float*)d_in[0];
    const float* pair   = (const float*)d_in[1];
    const float* norm_g = (const float*)d_in[base + 0];
    const float* norm_b = (const float*)d_in[base + 1];
    const float* Wqkv   = (const float*)d_in[base + 2];
    const float* bqkv   = (const float*)d_in[base + 3];
    const float* qln_g  = (const float*)d_in[base + 4];
    const float* qln_b  = (const float*)d_in[base + 5];
    const float* kln_g  = (const float*)d_in[base + 6];
    const float* kln_b  = (const float*)d_in[base + 7];
    const float* pair_g = (const float*)d_in[base + 8];
    const float* pair_b = (const float*)d_in[base + 9];
    const float* Wbias  = (const float*)d_in[base + 10];
    const float* Wproj  = (const float*)d_in[base + 11];
    const float* bproj  = (const float*)d_in[base + 12];
    float* out = (float*)d_out;

    precompute_gw<<<1, 384>>>(pair_g, pair_b, Wbias);              // 1
    ln_x_kernel<<<512, 192>>>(x, norm_g, norm_b);                  // 2
    gemm_qkv<<<dim3(36, 8), 256>>>(Wqkv, bqkv);                    // 3
    pair_bias_kernel<<<dim3(2, 512), 256>>>(pair);                 // 4 <- profiled
    qkv_prep_kernel<<<dim3(512, 3), 192>>>(qln_g, qln_b, kln_g, kln_b); // 5
    gemm_qk<<<dim3(4, 8, 12), 256>>>();                            // 6
    softmax_kernel<<<768, 256>>>();                                // 7
    gemm_pv<<<dim3(1, 8, 12), 256>>>();                            // 8
    gemm_proj<<<dim3(12, 8), 256>>>(Wproj, bproj, out);            // 9
}

// round 12
// speedup vs baseline: 1.5036x; 1.4439x over previous
#include <cuda_runtime.h>
#include <cstdint>
#include <math.h>

#define EPS 1e-5f
typedef unsigned long long ull;

// ---------------- f32x2 packed helpers ----------------
__device__ __forceinline__ ull pk2(float lo, float hi) {
    ull r; asm("mov.b64 %0,{%1,%2};" : "=l"(r) : "f"(lo), "f"(hi)); return r;
}
__device__ __forceinline__ void unpk2(float& lo, float& hi, ull v) {
    asm("mov.b64 {%0,%1},%2;" : "=f"(lo), "=f"(hi) : "l"(v));
}
__device__ __forceinline__ ull fma2(ull a, ull b, ull c) {
    ull d; asm("fma.rn.f32x2 %0,%1,%2,%3;" : "=l"(d) : "l"(a), "l"(b), "l"(c)); return d;
}
#define CP_ASYNC16(dst, src) \
    asm volatile("cp.async.ca.shared.global [%0], [%1], 16;" :: "r"(dst), "l"(src))
#define CP_COMMIT() asm volatile("cp.async.commit_group;" ::: "memory")
#define CP_WAIT1() asm volatile("cp.async.wait_group 1;" ::: "memory")
#define CP_WAIT0() asm volatile("cp.async.wait_group 0;" ::: "memory")

// ---------------- scratch (device globals; no allocations) ----------------
__device__ float g_xn[512 * 768];
__device__ float g_qkv[512 * 2304];
__device__ float g_qh[12 * 512 * 64];    // [h][i][d], q * scale
__device__ float g_kT[12 * 64 * 512];    // [h][d][j]
__device__ float g_vh[12 * 512 * 64];    // [h][j][d]
__device__ __align__(16) float g_gW[768 * 12];  // pair_g[c] * Wbias[c][h]
__device__ float g_GW[12];
__device__ float g_BW[12];
__device__ float g_bias[12 * 512 * 512]; // [h][i][j]; j>i stays 0 (.bss)
__device__ float g_sim[12 * 512 * 512];  // [h][i][j], reused as attn
__device__ float g_attout[512 * 768];    // [i][h*64+d]

// ---------------- precompute gW, GW, BW ----------------
__global__ void precompute_gw(const float* __restrict__ pg,
                              const float* __restrict__ pb,
                              const float* __restrict__ Wb) {
    int t = threadIdx.x; // 384
    for (int idx = t; idx < 768 * 12; idx += 384)
        g_gW[idx] = pg[idx / 12] * Wb[idx];
    int w = t >> 5, l = t & 31;
    if (w < 12) {
        float gw = 0.f, bw = 0.f;
        for (int c = l; c < 768; c += 32) {
            float wv = Wb[c * 12 + w];
            gw = fmaf(pg[c], wv, gw);
            bw = fmaf(pb[c], wv, bw);
        }
#pragma unroll
        for (int o = 16; o; o >>= 1) {
            gw += __shfl_xor_sync(0xffffffffu, gw, o);
            bw += __shfl_xor_sync(0xffffffffu, bw, o);
        }
        if (l == 0) { g_GW[w] = gw; g_BW[w] = bw; }
    }
}

// ---------------- LN(x) -> g_xn ----------------
__global__ void __launch_bounds__(192) ln_x_kernel(const float* __restrict__ x,
                                                   const float* __restrict__ g,
                                                   const float* __restrict__ b) {
    int i = blockIdx.x, t = threadIdx.x;
    int c = t * 4;
    float4 xv = *(const float4*)(x + i * 768 + c);
    float s = xv.x + xv.y + xv.z + xv.w;
    float ss = xv.x * xv.x + xv.y * xv.y + xv.z * xv.z + xv.w * xv.w;
    int lane = t & 31, w = t >> 5;
#pragma unroll
    for (int o = 16; o; o >>= 1) {
        s += __shfl_xor_sync(0xffffffffu, s, o);
        ss += __shfl_xor_sync(0xffffffffu, ss, o);
    }
    __shared__ float sh[6][2];
    if (lane == 0) { sh[w][0] = s; sh[w][1] = ss; }
    __syncthreads();
    float S = 0.f, SS = 0.f;
#pragma unroll
    for (int q = 0; q < 6; q++) { S += sh[q][0]; SS += sh[q][1]; }
    float m = S * (1.f / 768.f);
    float r = rsqrtf(SS * (1.f / 768.f) - m * m + EPS);
    float4 gv = *(const float4*)(g + c);
    float4 bv = *(const float4*)(b + c);
    float4 o;
    o.x = (xv.x - m) * r * gv.x + bv.x;
    o.y = (xv.y - m) * r * gv.y + bv.y;
    o.z = (xv.z - m) * r * gv.z + bv.z;
    o.w = (xv.w - m) * r * gv.w + bv.w;
    *(float4*)(g_xn + i * 768 + c) = o;
}

// ---------------- qkv split: QK-LN + head reshapes ----------------
__global__ void __launch_bounds__(192) qkv_prep_kernel(const float* __restrict__ qg,
                                                       const float* __restrict__ qb,
                                                       const float* __restrict__ kg,
                                                       const float* __restrict__ kb) {
    int i = blockIdx.x, p = blockIdx.y, t = threadIdx.x;
    int c = t * 4;
    const float* row = g_qkv + i * 2304 + p * 768;
    float4 xv = *(const float4*)(row + c);
    int h = c >> 6, d = c & 63;
    if (p == 2) {
        *(float4*)(g_vh + (h * 512 + i) * 64 + d) = xv;
        return;
    }
    float s = xv.x + xv.y + xv.z + xv.w;
    float ss = xv.x * xv.x + xv.y * xv.y + xv.z * xv.z + xv.w * xv.w;
    int lane = t & 31, w = t >> 5;
#pragma unroll
    for (int o = 16; o; o >>= 1) {
        s += __shfl_xor_sync(0xffffffffu, s, o);
        ss += __shfl_xor_sync(0xffffffffu, ss, o);
    }
    __shared__ float sh[6][2];
    if (lane == 0) { sh[w][0] = s; sh[w][1] = ss; }
    __syncthreads();
    float S = 0.f, SS = 0.f;
#pragma unroll
    for (int q = 0; q < 6; q++) { S += sh[q][0]; SS += sh[q][1]; }
    float m = S * (1.f / 768.f);
    float r = rsqrtf(SS * (1.f / 768.f) - m * m + EPS);
    const float* gg = (p == 0) ? qg : kg;
    const float* bb = (p == 0) ? qb : kb;
    float4 gv = *(const float4*)(gg + c);
    float4 bv = *(const float4*)(bb + c);
    float v0 = (xv.x - m) * r * gv.x + bv.x;
    float v1 = (xv.y - m) * r * gv.y + bv.y;
    float v2 = (xv.z - m) * r * gv.z + bv.z;
    float v3 = (xv.w - m) * r * gv.w + bv.w;
    if (p == 0) {
        float4 o = make_float4(v0 * 0.125f, v1 * 0.125f, v2 * 0.125f, v3 * 0.125f);
        *(float4*)(g_qh + (h * 512 + i) * 64 + d) = o;
    } else {
        float* kp = g_kT + h * (64 * 512) + d * 512 + i;
        kp[0] = v0; kp[512] = v1; kp[1024] = v2; kp[1536] = v3;
    }
}

// ---------------- pair-bias v5: cp.async staging + row-per-lane compute ----
// Block 256 thr (8 warps) covers a 256-row j-tile for query i; grid (2, 512).
// Warp w owns rows jw..jw+31 (one per lane, no reductions). Per 16-channel
// chunk: lanes cooperatively stage 32 rows x 64B via cp.async (coalesced,
// full sectors, double-buffered), then each lane computes its own row from
// smem (stride-20 -> conflict-free LDS.128). Weights: 36KB smem copy read as
// warp-uniform ulonglong2 (broadcast LDS.128, raw f32x2 pairs).
__global__ void __launch_bounds__(256) pair_bias_kernel(const float* __restrict__ pair) {
    int jt = blockIdx.x, i = blockIdx.y;
    if (jt * 256 > i) return;                 // block-uniform dead exit
    extern __shared__ __align__(16) ull dsm[];
    ull* sgW = dsm;                           // 4608 ull = 36 KB
    float* stg = (float*)(dsm + 4608);        // 8 warps x 2 bufs x 640 floats
    {
        const ull* src = (const ull*)g_gW;
        for (int idx = threadIdx.x; idx < 4608; idx += 256)
            sgW[idx] = src[idx];
    }
    __syncthreads();

    int w = threadIdx.x >> 5, lane = threadIdx.x & 31;
    int jw = jt * 256 + w * 32;
    if (jw > i) return;                       // dead warp (after the sync)
    int j = jw + lane;
    bool live = (j <= i);

    // loader mapping: flat f = p*32+lane -> row f>>2, 16B-segment f&3
    const float* lp[4];
    unsigned int sa[4];
    float* mybuf[2] = { stg + (w * 2 + 0) * 640, stg + (w * 2 + 1) * 640 };
#pragma unroll
    for (int p = 0; p < 4; p++) {
        int f = p * 32 + lane;
        int r = f >> 2, seg = f & 3;
        int jr = jw + r; if (jr > i) jr = i;  // clamped rows: L2-broadcast hits
        lp[p] = pair + ((size_t)i * 512 + jr) * 768 + seg * 4;
        sa[p] = (unsigned int)__cvta_generic_to_shared(mybuf[0] + r * 20 + seg * 4);
    }
    const unsigned int bufstep = 640 * 4;     // bytes between buffers

    ull S[6] = {0, 0, 0, 0, 0, 0};
    float s = 0.f, ss = 0.f;

    // prologue: stage chunk 0 into buffer 0
#pragma unroll
    for (int p = 0; p < 4; p++) CP_ASYNC16(sa[p], lp[p]);
    CP_COMMIT();

    for (int cc = 0; cc < 48; cc++) {
        int nb = (cc + 1) & 1;
        if (cc + 1 < 48) {
#pragma unroll
            for (int p = 0; p < 4; p++)
                CP_ASYNC16(sa[p] + nb * bufstep, lp[p] + (cc + 1) * 16);
            CP_COMMIT();
            CP_WAIT1();
        } else {
            CP_WAIT0();
        }
        __syncwarp();
        const float* xrow = mybuf[cc & 1] + lane * 20;
#pragma unroll
        for (int q = 0; q < 4; q++) {
            float4 xv = *(const float4*)(xrow + q * 4);
            float xs[4] = {xv.x, xv.y, xv.z, xv.w};
#pragma unroll
            for (int k = 0; k < 4; k++) {
                int ch = cc * 16 + q * 4 + k;
                const ulonglong2* wp = (const ulonglong2*)&sgW[ch * 6];
                ulonglong2 q0 = wp[0];
                ulonglong2 q1 = wp[1];
                ulonglong2 q2 = wp[2];
                float x = xs[k];
                s += x; ss = fmaf(x, x, ss);
                ull px = pk2(x, x);
                S[0] = fma2(px, q0.x, S[0]); S[1] = fma2(px, q0.y, S[1]);
                S[2] = fma2(px, q1.x, S[2]); S[3] = fma2(px, q1.y, S[3]);
                S[4] = fma2(px, q2.x, S[4]); S[5] = fma2(px, q2.y, S[5]);
            }
        }
        __syncwarp();                          // compute done before buf reuse
    }

    if (!live) return;
    float m = s * (1.f / 768.f);
    float r = rsqrtf(ss * (1.f / 768.f) - m * m + EPS);
    size_t pos = (size_t)i * 512 + j;
#pragma unroll
    for (int h2 = 0; h2 < 6; h2++) {
        float lo, hi; unpk2(lo, hi, S[h2]);
        g_bias[(size_t)(2 * h2) * (512 * 512) + pos] =
            r * (lo - m * __ldg(&g_GW[2 * h2])) + __ldg(&g_BW[2 * h2]);
        g_bias[(size_t)(2 * h2 + 1) * (512 * 512) + pos] =
            r * (hi - m * __ldg(&g_GW[2 * h2 + 1])) + __ldg(&g_BW[2 * h2 + 1]);
    }
}

// ---------------- f32x2 GEMM (R6 known-good): N-packed acc, double-buffered
template <int BM, int BN, int TM, int TN>
__device__ __forceinline__ void gemm2_body(const float* __restrict__ A,
                                           const float* __restrict__ B,
                                           float* __restrict__ C,
                                           const float* __restrict__ biasRow,
                                           const float* __restrict__ biasMat,
                                           int K, int lda, int ldb, int ldc) {
    constexpr int THREADS = (BM / TM) * (BN / TN);
    static_assert(THREADS == 256 && TM == 4, "shape");
    __shared__ __align__(16) float As[2][8][BM];
    __shared__ __align__(16) float Bs[2][8][BN];

    int tid = threadIdx.x;
    int tx = tid % (BN / TN), ty = tid / (BN / TN);
    int m0 = blockIdx.y * BM, n0 = blockIdx.x * BN;

    ull acc[TM][TN / 2];
#pragma unroll
    for (int ii = 0; ii < TM; ii++)
#pragma unroll
        for (int j2 = 0; j2 < TN / 2; j2++) acc[ii][j2] = 0ull;

    bool aact = tid < 2 * BM;
    bool bact = tid < 2 * BN;
    int ar = tid >> 1, ac = (tid & 1) * 4;
    int br = tid / (BN / 4), bc = (tid % (BN / 4)) * 4;

    float4 pa = make_float4(0.f, 0.f, 0.f, 0.f), pb = pa;
    if (aact) pa = *(const float4*)(A + (size_t)(m0 + ar) * lda + ac);
    if (bact) pb = *(const float4*)(B + (size_t)br * ldb + n0 + bc);
    if (aact) {
        As[0][ac + 0][ar] = pa.x; As[0][ac + 1][ar] = pa.y;
        As[0][ac + 2][ar] = pa.z; As[0][ac + 3][ar] = pa.w;
    }
    if (bact) *(float4*)&Bs[0][br][bc] = pb;
    __syncthreads();

    int sb = 0;
    for (int k0 = 0; k0 < K; k0 += 8) {
        bool more = (k0 + 8 < K);
        if (more) {
            if (aact) pa = *(const float4*)(A + (size_t)(m0 + ar) * lda + k0 + 8 + ac);
            if (bact) pb = *(const float4*)(B + (size_t)(k0 + 8 + br) * ldb + n0 + bc);
        }
#pragma unroll
        for (int kk = 0; kk < 8; kk++) {
            float4 av = *(const float4*)&As[sb][kk][ty * TM];
            float a4[4] = {av.x, av.y, av.z, av.w};
            ull b2[TN / 2];
            const ull* bp = (const ull*)&Bs[sb][kk][tx * TN];
#pragma unroll
            for (int j2 = 0; j2 < TN / 2; j2++) b2[j2] = bp[j2];
#pragma unroll
            for (int ii = 0; ii < TM; ii++) {
                ull aa = pk2(a4[ii], a4[ii]);
#pragma unroll
                for (int j2 = 0; j2 < TN / 2; j2++)
                    acc[ii][j2] = fma2(aa, b2[j2], acc[ii][j2]);
            }
        }
        if (more) {
            if (aact) {
                As[sb ^ 1][ac + 0][ar] = pa.x; As[sb ^ 1][ac + 1][ar] = pa.y;
                As[sb ^ 1][ac + 2][ar] = pa.z; As[sb ^ 1][ac + 3][ar] = pa.w;
            }
            if (bact) *(float4*)&Bs[sb ^ 1][br][bc] = pb;
            __syncthreads();
            sb ^= 1;
        }
    }

    float bv[TN];
#pragma unroll
    for (int c = 0; c < TN; c++)
        bv[c] = biasRow ? biasRow[n0 + tx * TN + c] : 0.f;

#pragma unroll
    for (int ii = 0; ii < TM; ii++) {
        int r = m0 + ty * TM + ii;
        float o[TN];
#pragma unroll
        for (int j2 = 0; j2 < TN / 2; j2++) {
            unpk2(o[2 * j2], o[2 * j2 + 1], acc[ii][j2]);
            o[2 * j2] += bv[2 * j2];
            o[2 * j2 + 1] += bv[2 * j2 + 1];
        }
        if (biasMat) {
            const float* bm = biasMat + (size_t)r * ldc + n0 + tx * TN;
#pragma unroll
            for (int c4 = 0; c4 < TN / 4; c4++) {
                float4 mv = *(const float4*)(bm + 4 * c4);
                o[4*c4+0] += mv.x; o[4*c4+1] += mv.y;
                o[4*c4+2] += mv.z; o[4*c4+3] += mv.w;
            }
        }
        float* cp = C + (size_t)r * ldc + n0 + tx * TN;
#pragma unroll
        for (int c4 = 0; c4 < TN / 4; c4++)
            *(float4*)(cp + 4 * c4) = make_float4(o[4*c4], o[4*c4+1], o[4*c4+2], o[4*c4+3]);
    }
}

__global__ void __launch_bounds__(256) gemm_qkv(const float* __restrict__ W,
                                                const float* __restrict__ bias) {
    gemm2_body<64, 64, 4, 4>(g_xn, W, g_qkv, bias, nullptr, 768, 768, 2304, 2304);
}
__global__ void __launch_bounds__(256) gemm_qk() {
    int h = blockIdx.z;
    gemm2_body<64, 128, 4, 8>(g_qh + h * (512 * 64), g_kT + h * (64 * 512),
                              g_sim + (size_t)h * (512 * 512), nullptr,
                              g_bias + (size_t)h * (512 * 512), 64, 64, 512, 512);
}
__global__ void __launch_bounds__(256) gemm_pv() {
    int h = blockIdx.z;
    gemm2_body<64, 64, 4, 4>(g_sim + (size_t)h * (512 * 512), g_vh + h * (512 * 64),
                             g_attout + h * 64, nullptr, nullptr, 512, 512, 64, 768);
}
__global__ void __launch_bounds__(256) gemm_proj(const float* __restrict__ W,
                                                 const float* __restrict__ bias,
                                                 float* __restrict__ out) {
    gemm2_body<64, 64, 4, 4>(g_attout, W, out, bias, nullptr, 768, 768, 768, 768);
}

// ---------------- softmax: warp per (h,i) row, registers only ----------------
__global__ void __launch_bounds__(256) softmax_kernel() {
    int warp = threadIdx.x >> 5, lane = threadIdx.x & 31;
    int rowid = blockIdx.x * 8 + warp;              // 0..6143
    float* row = g_sim + (size_t)rowid * 512;
    float v[16];
    float4* rp = (float4*)(row + lane * 16);
    float4 r0 = rp[0], r1 = rp[1], r2 = rp[2], r3 = rp[3];
    v[0]=r0.x; v[1]=r0.y; v[2]=r0.z; v[3]=r0.w;
    v[4]=r1.x; v[5]=r1.y; v[6]=r1.z; v[7]=r1.w;
    v[8]=r2.x; v[9]=r2.y; v[10]=r2.z; v[11]=r2.w;
    v[12]=r3.x; v[13]=r3.y; v[14]=r3.z; v[15]=r3.w;
    float m = v[0];
#pragma unroll
    for (int e = 1; e < 16; e++) m = fmaxf(m, v[e]);
#pragma unroll
    for (int o = 16; o; o >>= 1) m = fmaxf(m, __shfl_xor_sync(0xffffffffu, m, o));
    float s = 0.f;
#pragma unroll
    for (int e = 0; e < 16; e++) { v[e] = __expf(v[e] - m); s += v[e]; }
#pragma unroll
    for (int o = 16; o; o >>= 1) s += __shfl_xor_sync(0xffffffffu, s, o);
    float inv = __fdividef(1.f, s);
    rp[0] = make_float4(v[0]*inv, v[1]*inv, v[2]*inv, v[3]*inv);
    rp[1] = make_float4(v[4]*inv, v[5]*inv, v[6]*inv, v[7]*inv);
    rp[2] = make_float4(v[8]*inv, v[9]*inv, v[10]*inv, v[11]*inv);
    rp[3] = make_float4(v[12]*inv, v[13]*inv, v[14]*inv, v[15]*inv);
}

// ---------------- launch ----------------
extern "C" void kernel_launch(void* const* d_in, const int* in_sizes, int n_in,
                              void* d_out, int out_size) {
    int base = n_in - 13;                     // norm_g index (mask-type agnostic)
    const float* x      = (const float*)d_in[0];
    const float* pair   = (const float*)d_in[1];
    const float* norm_g = (const float*)d_in[base + 0];
    const float* norm_b = (const float*)d_in[base + 1];
    const float* Wqkv   = (const float*)d_in[base + 2];
    const float* bqkv   = (const float*)d_in[base + 3];
    const float* qln_g  = (const float*)d_in[base + 4];
    const float* qln_b  = (const float*)d_in[base + 5];
    const float* kln_g  = (const float*)d_in[base + 6];
    const float* kln_b  = (const float*)d_in[base + 7];
    const float* pair_g = (const float*)d_in[base + 8];
    const float* pair_b = (const float*)d_in[base + 9];
    const float* Wbias  = (const float*)d_in[base + 10];
    const float* Wproj  = (const float*)d_in[base + 11];
    const float* bproj  = (const float*)d_in[base + 12];
    float* out = (float*)d_out;

    const int PB_SMEM = 4608 * 8 + 8 * 2 * 640 * 4;   // 36KB weights + 40KB staging
    cudaFuncSetAttribute(pair_bias_kernel,
                         cudaFuncAttributeMaxDynamicSharedMemorySize, PB_SMEM);

    precompute_gw<<<1, 384>>>(pair_g, pair_b, Wbias);              // 1
    ln_x_kernel<<<512, 192>>>(x, norm_g, norm_b);                  // 2
    gemm_qkv<<<dim3(36, 8), 256>>>(Wqkv, bqkv);                    // 3
    pair_bias_kernel<<<dim3(2, 512), 256, PB_SMEM>>>(pair);        // 4 <- profiled
    qkv_prep_kernel<<<dim3(512, 3), 192>>>(qln_g, qln_b, kln_g, kln_b); // 5
    gemm_qk<<<dim3(4, 8, 12), 256>>>();                            // 6
    softmax_kernel<<<768, 256>>>();                                // 7
    gemm_pv<<<dim3(1, 8, 12), 256>>>();                            // 8
    gemm_proj<<<dim3(12, 8), 256>>>(Wproj, bproj, out);            // 9
}